// round 16
// baseline (speedup 1.0000x reference)
#include <cuda_runtime.h>
#include <cuda_fp16.h>
#include <math.h>
#include <stdint.h>

// Problem dims: B=16, S=1024, H=1024, K=256
#define BATCH 16
#define SEQ   1024
#define HID   1024
#define KIDX  256
#define MTOT  (BATCH * KIDX)      // 4096 rows per span
#define MBT   (MTOT / 16)          // 256 m-blocks (16 rows)
#define NBT   (HID / 8)            // 128 n-blocks (8 cols)
#define KB16T (HID / 16)           // 64 k16-blocks

// GEMM tiling: CTA 64x128, 8 warps (2x4), warp tile 32x32, k-chunk 64 (4 kb16)
#define TM    64
#define TN    128
#define NCH   (HID / 64)           // 16 chunks
#define STAGES 3
#define STAGE_U32 16384            // u32 per stage: A 4096 + B 12288 (64KB)
#define SMEM_BYTES (STAGES * STAGE_U32 * 4)   // 192KB

// ---------------- device scratch (fp16 fragment-ordered) ----------------
__device__ uint4 g_Af[2][2][(size_t)MBT * KB16T * 32];
__device__ uint2 g_Wf[2][3][(size_t)NBT * KB16T * 32];
__device__ float g_c12[2][HID];
__device__ int   g_is64[2];

// ---------------- helpers ----------------
__device__ __forceinline__ uint32_t smem_u32(const void* p) {
    uint32_t a;
    asm("{ .reg .u64 t; cvta.to.shared.u64 t, %1; cvt.u32.u64 %0, t; }" : "=r"(a) : "l"(p));
    return a;
}
__device__ __forceinline__ uint32_t pack2(float lo, float hi) {
    __half2 h = __floats2half2_rn(lo, hi);
    return *(uint32_t*)&h;
}

#define MMA_F16(c, a, b_) \
    asm volatile("mma.sync.aligned.m16n8k16.row.col.f32.f16.f16.f32 " \
        "{%0,%1,%2,%3}, {%4,%5,%6,%7}, {%8,%9}, {%0,%1,%2,%3};" \
        : "+f"((c)[0]), "+f"((c)[1]), "+f"((c)[2]), "+f"((c)[3]) \
        : "r"((a).x), "r"((a).y), "r"((a).z), "r"((a).w), \
          "r"((b_).x), "r"((b_).y))

// ---------------- prep ----------------
__global__ void detect_idx_kernel(const unsigned int* __restrict__ prem_raw) {
    if (threadIdx.x == 0) {
        int all_zero = 1;
        #pragma unroll
        for (int i = 0; i < 32; i++)
            if (prem_raw[2 * i + 1] != 0u) all_zero = 0;
        g_is64[0] = all_zero;
        g_is64[1] = 0;
    }
}

// Merged prep: blocks [0,256) = weights role (nb, span), [256,1280) = gather role.
#define ROWP_U32 516   // padded smem row stride (u32) -> conflict-free
__global__ __launch_bounds__(256)
void prep_all(const float* __restrict__ x,
              const void* __restrict__ prem, const void* __restrict__ hypo,
              const float* __restrict__ Wp1, const float* __restrict__ Wp2,
              const float* __restrict__ Wp3, const float* __restrict__ Wp4,
              const float* __restrict__ Wh1, const float* __restrict__ Wh2,
              const float* __restrict__ Wh3, const float* __restrict__ Wh4,
              const float* __restrict__ bp1, const float* __restrict__ bp2,
              const float* __restrict__ bh1, const float* __restrict__ bh2) {
    __shared__ uint32_t sm[16 * ROWP_U32];
    __shared__ int sidx[16];
    const int blk  = blockIdx.x;
    const int lane = threadIdx.x & 31;
    const int w    = threadIdx.x >> 5;

    if (blk < 256) {
        // ---- weights role ----
        const int nb   = blk & 127;
        const int span = blk >> 7;
        const float* W1 = span ? Wh1 : Wp1;
        const float* W2 = span ? Wh2 : Wp2;
        const float* W3 = span ? Wh3 : Wp3;
        const float* W4 = span ? Wh4 : Wp4;
        if (nb < 4) {
            const int i = nb * 256 + threadIdx.x;
            g_c12[span][i] = span ? (bh1[i] + bh2[i]) : (bp1[i] + bp2[i]);
        }
        const int n  = nb * 8 + (lane >> 2);
        const int c2 = (lane & 3) * 2;
        uint2* d13 = g_Wf[span][0] + (size_t)nb * KB16T * 32;
        uint2* d23 = g_Wf[span][1] + (size_t)nb * KB16T * 32;
        uint2* d4  = g_Wf[span][2] + (size_t)nb * KB16T * 32;
        #pragma unroll
        for (int i = 0; i < 8; i++) {
            const int kb16 = w + 8 * i;
            const size_t ka = (size_t)n * HID + kb16 * 16 + c2;
            float2 w1a = __ldg((const float2*)(W1 + ka));
            float2 w1b = __ldg((const float2*)(W1 + ka + 8));
            float2 w2a = __ldg((const float2*)(W2 + ka));
            float2 w2b = __ldg((const float2*)(W2 + ka + 8));
            float2 w3a = __ldg((const float2*)(W3 + ka));
            float2 w3b = __ldg((const float2*)(W3 + ka + 8));
            float2 w4a = __ldg((const float2*)(W4 + ka));
            float2 w4b = __ldg((const float2*)(W4 + ka + 8));
            const size_t o = (size_t)kb16 * 32 + lane;
            d13[o] = make_uint2(pack2(w1a.x + w3a.x, w1a.y + w3a.y),
                                pack2(w1b.x + w3b.x, w1b.y + w3b.y));
            d23[o] = make_uint2(pack2(w2a.x - w3a.x, w2a.y - w3a.y),
                                pack2(w2b.x - w3b.x, w2b.y - w3b.y));
            d4[o]  = make_uint2(pack2(w4a.x, w4a.y), pack2(w4b.x, w4b.y));
        }
        return;
    }

    // ---- gather role ----
    const int g     = blk - 256;
    const int mb    = g & 255;
    const int which = (g >> 8) & 1;
    const int span  = g >> 9;
    const void* idx_raw = span ? hypo : prem;

    if (threadIdx.x < 16) {
        const int m = mb * 16 + threadIdx.x;
        const int b = m >> 8;
        const int k = m & (KIDX - 1);
        const long off = ((long)b * 2 + which) * KIDX + k;
        int s;
        if (g_is64[span]) s = (int)((const long long*)idx_raw)[off];
        else              s = ((const int*)idx_raw)[off];
        sidx[threadIdx.x] = b * SEQ + s;
    }
    __syncthreads();

    // Stage: warp w copies rows 2w, 2w+1 with coalesced float4; fp16 convert.
    #pragma unroll
    for (int rr = 0; rr < 2; rr++) {
        const int row = 2 * w + rr;
        const float4* src = (const float4*)(x + (size_t)sidx[row] * HID);
        uint32_t* dstrow = sm + row * ROWP_U32;
        #pragma unroll
        for (int i = 0; i < 8; i++) {
            float4 v = __ldg(src + lane + 32 * i);
            dstrow[2 * (lane + 32 * i)]     = pack2(v.x, v.y);
            dstrow[2 * (lane + 32 * i) + 1] = pack2(v.z, v.w);
        }
    }
    __syncthreads();

    // Fragment phase: thread (w,lane) emits kb16 = w+8i
    const int r = lane >> 2;
    const int c = lane & 3;
    uint4* dst = g_Af[span][which] + (size_t)mb * KB16T * 32;
    #pragma unroll
    for (int i = 0; i < 8; i++) {
        const int kb16 = w + 8 * i;
        const int base = kb16 * 8 + c;
        uint4 o;
        o.x = sm[r * ROWP_U32 + base];
        o.y = sm[(r + 8) * ROWP_U32 + base];
        o.z = sm[r * ROWP_U32 + base + 4];
        o.w = sm[(r + 8) * ROWP_U32 + base + 4];
        dst[(size_t)kb16 * 32 + lane] = o;
    }
}

// ---------------- main fused GEMM (fp16 mma.sync, fragment smem) ---------
// out = tanh(accL + c12 + (ac4s+b4)*(ac4e+b4))
__global__ __launch_bounds__(256, 1)
void gemm_kernel(const float* __restrict__ bp4, const float* __restrict__ bh4,
                 float* __restrict__ out) {
    extern __shared__ uint32_t smu[];
    const int tid  = threadIdx.x;
    const int wid  = tid >> 5;
    const int lane = tid & 31;
    const int span = blockIdx.z;
    const int n0   = blockIdx.x * TN;
    const int m0   = blockIdx.y * TM;
    const int mb0  = m0 >> 4;
    const int nb0  = n0 >> 3;
    const int wm   = wid >> 2;
    const int wn   = wid & 3;

    const uint4* gb[16];
    int so[16], adv[16];
    #pragma unroll
    for (int s = 0; s < 16; s++) {
        const int v = s * 256 + tid;
        if (v < 1024) {
            const int l   = v & 31;
            const int j   = (v >> 5) & 3;
            const int mbl = (v >> 7) & 3;
            const int o   = v >> 9;
            gb[s]  = g_Af[span][o] + (size_t)(mb0 + mbl) * (KB16T * 32) + j * 32 + l;
            so[s]  = v * 4;
            adv[s] = 4 * 32;
        } else {
            const int u  = v - 1024;
            const int q  = u & 15;
            const int j  = (u >> 4) & 3;
            const int nb = (u >> 6) & 15;
            const int w  = u >> 10;
            gb[s]  = (const uint4*)g_Wf[span][w] +
                     (size_t)(nb0 + nb) * (KB16T * 16) + j * 16 + q;
            so[s]  = 4096 + u * 4;
            adv[s] = 4 * 16;
        }
    }
    const uint32_t sbu = smem_u32(smu);

#define LOAD_CHUNK(ch, st) do {                                                  \
        _Pragma("unroll")                                                        \
        for (int _s = 0; _s < 16; _s++) {                                        \
            uint32_t _d = sbu + (uint32_t)(((st) * STAGE_U32 + so[_s]) * 4);     \
            asm volatile("cp.async.cg.shared.global [%0], [%1], 16;"             \
                         :: "r"(_d), "l"(gb[_s] + (size_t)(ch) * adv[_s])        \
                         : "memory");                                            \
        }                                                                        \
    } while (0)

    const int aOff = lane * 4;
    const int bOff = 4096 + lane * 2;

#define LOAD_FRAGS(af, bf, S0, kbl) do {                                         \
        _Pragma("unroll")                                                        \
        for (int _o = 0; _o < 2; _o++)                                           \
            _Pragma("unroll")                                                    \
            for (int _mt = 0; _mt < 2; _mt++)                                    \
                (af)[_o][_mt] = *(const uint4*)(smu + (S0) + aOff +              \
                            ((_o * 4 + wm * 2 + _mt) * 4 + (kbl)) * 128);        \
        _Pragma("unroll")                                                        \
        for (int _w = 0; _w < 3; _w++)                                           \
            _Pragma("unroll")                                                    \
            for (int _nt = 0; _nt < 4; _nt++)                                    \
                (bf)[_w][_nt] = *(const uint2*)(smu + (S0) + bOff +              \
                            ((_w * 16 + wn * 4 + _nt) * 4 + (kbl)) * 64);        \
    } while (0)

#define DO_MMAS(af, bf) do {                                                     \
        _Pragma("unroll")                                                        \
        for (int _nt = 0; _nt < 4; _nt++) {                                      \
            MMA_F16(accL[0][_nt], (af)[0][0], (bf)[0][_nt]);                     \
            MMA_F16(accL[1][_nt], (af)[0][1], (bf)[0][_nt]);                     \
            MMA_F16(ac4s[0][_nt], (af)[0][0], (bf)[2][_nt]);                     \
            MMA_F16(ac4s[1][_nt], (af)[0][1], (bf)[2][_nt]);                     \
            MMA_F16(ac4e[0][_nt], (af)[1][0], (bf)[2][_nt]);                     \
            MMA_F16(ac4e[1][_nt], (af)[1][1], (bf)[2][_nt]);                     \
            MMA_F16(accL[0][_nt], (af)[1][0], (bf)[1][_nt]);                     \
            MMA_F16(accL[1][_nt], (af)[1][1], (bf)[1][_nt]);                     \
        }                                                                        \
    } while (0)

    float accL[2][4][4] = {}, ac4s[2][4][4] = {}, ac4e[2][4][4] = {};

    // prologue: 2 chunks in flight (stage = ch % 3)
    LOAD_CHUNK(0, 0);
    asm volatile("cp.async.commit_group;" ::: "memory");
    LOAD_CHUNK(1, 1);
    asm volatile("cp.async.commit_group;" ::: "memory");

    int st = 0;                        // stage of chunk ch (= ch % 3)
    for (int ch = 0; ch < NCH; ch++) {
        // Barrier 1: all warps finished reading chunk ch-1 -> safe to
        // overwrite its stage with chunk ch+2.
        __syncthreads();
        if (ch + 2 < NCH) {
            int stn = st + 2; if (stn >= STAGES) stn -= STAGES;
            LOAD_CHUNK(ch + 2, stn);
        }
        asm volatile("cp.async.commit_group;" ::: "memory");
        // wait: pending groups = ch+1, ch+2 -> this thread's chunk-ch copies done
        asm volatile("cp.async.wait_group 2;" ::: "memory");
        // Barrier 2: every thread has waited -> ALL chunk-ch copies visible.
        __syncthreads();

        const int S0 = st * STAGE_U32;
        st = (st + 1 == STAGES) ? 0 : st + 1;

        // fragment double-buffer across kbl
        uint4 afc[2][2]; uint2 bfc[3][4];
        LOAD_FRAGS(afc, bfc, S0, 0);
        #pragma unroll
        for (int kbl = 0; kbl < 4; kbl++) {
            uint4 afn[2][2]; uint2 bfn[3][4];
            if (kbl < 3) LOAD_FRAGS(afn, bfn, S0, kbl + 1);
            DO_MMAS(afc, bfc);
            if (kbl < 3) {
                #pragma unroll
                for (int o = 0; o < 2; o++)
                    #pragma unroll
                    for (int mt = 0; mt < 2; mt++) afc[o][mt] = afn[o][mt];
                #pragma unroll
                for (int w = 0; w < 3; w++)
                    #pragma unroll
                    for (int nt = 0; nt < 4; nt++) bfc[w][nt] = bfn[w][nt];
            }
        }
    }

    // epilogue
    const float* b4p  = span ? bh4 : bp4;
    const float* c12p = g_c12[span];
    float* outp = out + (size_t)span * MTOT * HID;

    #pragma unroll
    for (int mt = 0; mt < 2; mt++) {
        const int r0 = m0 + wm * 32 + mt * 16 + (lane >> 2);
        #pragma unroll
        for (int nt = 0; nt < 4; nt++) {
            const int o = n0 + wn * 32 + nt * 8 + (lane & 3) * 2;
            const float c0 = c12p[o],   c1 = c12p[o + 1];
            const float d0 = b4p[o],    d1 = b4p[o + 1];
            float v0 = accL[mt][nt][0] + c0 + (ac4s[mt][nt][0] + d0) * (ac4e[mt][nt][0] + d0);
            float v1 = accL[mt][nt][1] + c1 + (ac4s[mt][nt][1] + d1) * (ac4e[mt][nt][1] + d1);
            *(float2*)&outp[(size_t)r0 * HID + o] = make_float2(tanhf(v0), tanhf(v1));
            float v2 = accL[mt][nt][2] + c0 + (ac4s[mt][nt][2] + d0) * (ac4e[mt][nt][2] + d0);
            float v3 = accL[mt][nt][3] + c1 + (ac4s[mt][nt][3] + d1) * (ac4e[mt][nt][3] + d1);
            *(float2*)&outp[(size_t)(r0 + 8) * HID + o] = make_float2(tanhf(v2), tanhf(v3));
        }
    }
}

// ---------------- launch ----------------
extern "C" void kernel_launch(void* const* d_in, const int* in_sizes, int n_in,
                              void* d_out, int out_size) {
    const float* x    = (const float*)d_in[0];
    const void*  prem = d_in[1];
    const void*  hypo = d_in[2];
    const float* Wp1 = (const float*)d_in[3];
    const float* bp1 = (const float*)d_in[4];
    const float* Wp2 = (const float*)d_in[5];
    const float* bp2 = (const float*)d_in[6];
    const float* Wp3 = (const float*)d_in[7];
    const float* Wp4 = (const float*)d_in[9];
    const float* bp4 = (const float*)d_in[10];
    const float* Wh1 = (const float*)d_in[11];
    const float* bh1 = (const float*)d_in[12];
    const float* Wh2 = (const float*)d_in[13];
    const float* bh2 = (const float*)d_in[14];
    const float* Wh3 = (const float*)d_in[15];
    const float* Wh4 = (const float*)d_in[17];
    const float* bh4 = (const float*)d_in[18];
    float* out = (float*)d_out;

    detect_idx_kernel<<<1, 32>>>((const unsigned int*)prem);

    prep_all<<<1280, 256>>>(x, prem, hypo,
                            Wp1, Wp2, Wp3, Wp4, Wh1, Wh2, Wh3, Wh4,
                            bp1, bp2, bh1, bh2);

    cudaFuncSetAttribute(gemm_kernel, cudaFuncAttributeMaxDynamicSharedMemorySize, SMEM_BYTES);
    gemm_kernel<<<dim3(HID / TN, MTOT / TM, 2), 256, SMEM_BYTES>>>(bp4, bh4, out);
}

// round 17
// speedup vs baseline: 1.0692x; 1.0692x over previous
#include <cuda_runtime.h>
#include <cuda_fp16.h>
#include <math.h>
#include <stdint.h>

// Problem dims: B=16, S=1024, H=1024, K=256
#define BATCH 16
#define SEQ   1024
#define HID   1024
#define KIDX  256
#define MTOT  (BATCH * KIDX)      // 4096 rows per span
#define MBT   (MTOT / 16)          // 256 m-blocks (16 rows)
#define NBT   (HID / 8)            // 128 n-blocks (8 cols)
#define KB16T (HID / 16)           // 64 k16-blocks

// GEMM tiling: CTA 64x128, 8 warps (2x4), warp tile 32x32, k-chunk 64 (4 kb16)
#define TM    64
#define TN    128
#define NCH   (HID / 64)           // 16 chunks
#define STAGES 3
#define STAGE_U32 16384            // u32 per stage: A 4096 + B 12288 (64KB)
#define SMEM_BYTES (STAGES * STAGE_U32 * 4)   // 192KB

// ---------------- device scratch (fp16 fragment-ordered) ----------------
__device__ uint4 g_Af[2][2][(size_t)MBT * KB16T * 32];
__device__ uint2 g_Wf[2][3][(size_t)NBT * KB16T * 32];
__device__ float g_c12[2][HID];

// ---------------- helpers ----------------
__device__ __forceinline__ uint32_t smem_u32(const void* p) {
    uint32_t a;
    asm("{ .reg .u64 t; cvta.to.shared.u64 t, %1; cvt.u32.u64 %0, t; }" : "=r"(a) : "l"(p));
    return a;
}
__device__ __forceinline__ uint32_t pack2(float lo, float hi) {
    __half2 h = __floats2half2_rn(lo, hi);
    return *(uint32_t*)&h;
}

#define MMA_F16(c, a, b_) \
    asm volatile("mma.sync.aligned.m16n8k16.row.col.f32.f16.f16.f32 " \
        "{%0,%1,%2,%3}, {%4,%5,%6,%7}, {%8,%9}, {%0,%1,%2,%3};" \
        : "+f"((c)[0]), "+f"((c)[1]), "+f"((c)[2]), "+f"((c)[3]) \
        : "r"((a).x), "r"((a).y), "r"((a).z), "r"((a).w), \
          "r"((b_).x), "r"((b_).y))

// ---------------- merged prep ----------------
// blocks [0,256) = weights role (nb, span), [256,1280) = gather role.
#define ROWP_U32 516   // padded smem row stride (u32) -> conflict-free
__global__ __launch_bounds__(256)
void prep_all(const float* __restrict__ x,
              const void* __restrict__ prem, const void* __restrict__ hypo,
              const float* __restrict__ Wp1, const float* __restrict__ Wp2,
              const float* __restrict__ Wp3, const float* __restrict__ Wp4,
              const float* __restrict__ Wh1, const float* __restrict__ Wh2,
              const float* __restrict__ Wh3, const float* __restrict__ Wh4,
              const float* __restrict__ bp1, const float* __restrict__ bp2,
              const float* __restrict__ bh1, const float* __restrict__ bh2) {
    __shared__ uint32_t sm[16 * ROWP_U32];
    __shared__ int sidx[16];
    __shared__ int is64sh;
    const int blk  = blockIdx.x;
    const int lane = threadIdx.x & 31;
    const int w    = threadIdx.x >> 5;

    if (blk < 256) {
        // ---- weights role ----
        const int nb   = blk & 127;
        const int span = blk >> 7;
        const float* W1 = span ? Wh1 : Wp1;
        const float* W2 = span ? Wh2 : Wp2;
        const float* W3 = span ? Wh3 : Wp3;
        const float* W4 = span ? Wh4 : Wp4;
        if (nb < 4) {
            const int i = nb * 256 + threadIdx.x;
            g_c12[span][i] = span ? (bh1[i] + bh2[i]) : (bp1[i] + bp2[i]);
        }
        const int n  = nb * 8 + (lane >> 2);
        const int c2 = (lane & 3) * 2;
        uint2* d13 = g_Wf[span][0] + (size_t)nb * KB16T * 32;
        uint2* d23 = g_Wf[span][1] + (size_t)nb * KB16T * 32;
        uint2* d4  = g_Wf[span][2] + (size_t)nb * KB16T * 32;
        #pragma unroll
        for (int i = 0; i < 8; i++) {
            const int kb16 = w + 8 * i;
            const size_t ka = (size_t)n * HID + kb16 * 16 + c2;
            float2 w1a = __ldg((const float2*)(W1 + ka));
            float2 w1b = __ldg((const float2*)(W1 + ka + 8));
            float2 w2a = __ldg((const float2*)(W2 + ka));
            float2 w2b = __ldg((const float2*)(W2 + ka + 8));
            float2 w3a = __ldg((const float2*)(W3 + ka));
            float2 w3b = __ldg((const float2*)(W3 + ka + 8));
            float2 w4a = __ldg((const float2*)(W4 + ka));
            float2 w4b = __ldg((const float2*)(W4 + ka + 8));
            const size_t o = (size_t)kb16 * 32 + lane;
            d13[o] = make_uint2(pack2(w1a.x + w3a.x, w1a.y + w3a.y),
                                pack2(w1b.x + w3b.x, w1b.y + w3b.y));
            d23[o] = make_uint2(pack2(w2a.x - w3a.x, w2a.y - w3a.y),
                                pack2(w2b.x - w3b.x, w2b.y - w3b.y));
            d4[o]  = make_uint2(pack2(w4a.x, w4a.y), pack2(w4b.x, w4b.y));
        }
        return;
    }

    // ---- gather role ----
    const int g     = blk - 256;
    const int mb    = g & 255;
    const int which = (g >> 8) & 1;
    const int span  = g >> 9;
    const void* idx_raw = span ? hypo : prem;

    // local int64/int32 detection: int64 indices (< 2^32) have all-zero odd
    // u32 words; int32 buffers have random values (P[all 32 zero] ~ 1024^-32).
    if (threadIdx.x == 0) {
        const unsigned int* p = (const unsigned int*)idx_raw;
        int all_zero = 1;
        #pragma unroll
        for (int i = 0; i < 32; i++)
            if (p[2 * i + 1] != 0u) all_zero = 0;
        is64sh = all_zero;
    }
    __syncthreads();

    if (threadIdx.x < 16) {
        const int m = mb * 16 + threadIdx.x;
        const int b = m >> 8;
        const int k = m & (KIDX - 1);
        const long off = ((long)b * 2 + which) * KIDX + k;
        int s;
        if (is64sh) s = (int)((const long long*)idx_raw)[off];
        else        s = ((const int*)idx_raw)[off];
        sidx[threadIdx.x] = b * SEQ + s;
    }
    __syncthreads();

    // Stage: warp w copies rows 2w, 2w+1 with coalesced float4; fp16 convert.
    #pragma unroll
    for (int rr = 0; rr < 2; rr++) {
        const int row = 2 * w + rr;
        const float4* src = (const float4*)(x + (size_t)sidx[row] * HID);
        uint32_t* dstrow = sm + row * ROWP_U32;
        #pragma unroll
        for (int i = 0; i < 8; i++) {
            float4 v = __ldg(src + lane + 32 * i);
            dstrow[2 * (lane + 32 * i)]     = pack2(v.x, v.y);
            dstrow[2 * (lane + 32 * i) + 1] = pack2(v.z, v.w);
        }
    }
    __syncthreads();

    // Fragment phase: thread (w,lane) emits kb16 = w+8i
    const int r = lane >> 2;
    const int c = lane & 3;
    uint4* dst = g_Af[span][which] + (size_t)mb * KB16T * 32;
    #pragma unroll
    for (int i = 0; i < 8; i++) {
        const int kb16 = w + 8 * i;
        const int base = kb16 * 8 + c;
        uint4 o;
        o.x = sm[r * ROWP_U32 + base];
        o.y = sm[(r + 8) * ROWP_U32 + base];
        o.z = sm[r * ROWP_U32 + base + 4];
        o.w = sm[(r + 8) * ROWP_U32 + base + 4];
        dst[(size_t)kb16 * 32 + lane] = o;
    }
}

// ---------------- main fused GEMM (fp16 mma.sync, fragment smem) ---------
// out = tanh(accL + c12 + (ac4s+b4)*(ac4e+b4))
__global__ __launch_bounds__(256, 1)
void gemm_kernel(const float* __restrict__ bp4, const float* __restrict__ bh4,
                 float* __restrict__ out) {
    extern __shared__ uint32_t smu[];
    const int tid  = threadIdx.x;
    const int wid  = tid >> 5;
    const int lane = tid & 31;
    const int span = blockIdx.z;
    const int n0   = blockIdx.x * TN;
    const int m0   = blockIdx.y * TM;
    const int mb0  = m0 >> 4;
    const int nb0  = n0 >> 3;
    const int wm   = wid >> 2;
    const int wn   = wid & 3;

    const uint4* gb[16];
    int so[16], adv[16];
    #pragma unroll
    for (int s = 0; s < 16; s++) {
        const int v = s * 256 + tid;
        if (v < 1024) {
            const int l   = v & 31;
            const int j   = (v >> 5) & 3;
            const int mbl = (v >> 7) & 3;
            const int o   = v >> 9;
            gb[s]  = g_Af[span][o] + (size_t)(mb0 + mbl) * (KB16T * 32) + j * 32 + l;
            so[s]  = v * 4;
            adv[s] = 4 * 32;
        } else {
            const int u  = v - 1024;
            const int q  = u & 15;
            const int j  = (u >> 4) & 3;
            const int nb = (u >> 6) & 15;
            const int w  = u >> 10;
            gb[s]  = (const uint4*)g_Wf[span][w] +
                     (size_t)(nb0 + nb) * (KB16T * 16) + j * 16 + q;
            so[s]  = 4096 + u * 4;
            adv[s] = 4 * 16;
        }
    }
    const uint32_t sbu = smem_u32(smu);

// issue 4 of the 16 per-chunk cp.asyncs (slot group q = 0..3)
#define LOAD_QUARTER(ch, st, q) do {                                             \
        _Pragma("unroll")                                                        \
        for (int _s = (q) * 4; _s < (q) * 4 + 4; _s++) {                         \
            uint32_t _d = sbu + (uint32_t)(((st) * STAGE_U32 + so[_s]) * 4);     \
            asm volatile("cp.async.cg.shared.global [%0], [%1], 16;"             \
                         :: "r"(_d), "l"(gb[_s] + (size_t)(ch) * adv[_s])        \
                         : "memory");                                            \
        }                                                                        \
    } while (0)

    const int aOff = lane * 4;
    const int bOff = 4096 + lane * 2;

    float accL[2][4][4] = {}, ac4s[2][4][4] = {}, ac4e[2][4][4] = {};

    // prologue: 2 chunks in flight (stage = ch % 3)
    #pragma unroll
    for (int q = 0; q < 4; q++) LOAD_QUARTER(0, 0, q);
    asm volatile("cp.async.commit_group;" ::: "memory");
    #pragma unroll
    for (int q = 0; q < 4; q++) LOAD_QUARTER(1, 1, q);
    asm volatile("cp.async.commit_group;" ::: "memory");

    int st = 0;                        // stage of chunk ch (= ch % 3)
    for (int ch = 0; ch < NCH; ch++) {
        // newest pending group = chunk ch+1 -> wait_group 1 completes chunk ch
        asm volatile("cp.async.wait_group 1;" ::: "memory");
        // single barrier: (a) chunk-ch copies visible to all warps,
        // (b) all warps' chunk ch-1 reads done -> safe to overwrite its stage
        //     (the ch+2 cp.asyncs below are issued after this barrier).
        __syncthreads();

        const int S0 = st * STAGE_U32;
        st = (st + 1 == STAGES) ? 0 : st + 1;
        int stn = st + 1; if (stn >= STAGES) stn -= STAGES;   // stage of ch+2
        const bool more = (ch + 2 < NCH);

        #pragma unroll
        for (int kbl = 0; kbl < 4; kbl++) {
            uint4 af[2][2];
            #pragma unroll
            for (int o = 0; o < 2; o++)
                #pragma unroll
                for (int mt = 0; mt < 2; mt++)
                    af[o][mt] = *(const uint4*)(smu + S0 + aOff +
                                ((o * 4 + wm * 2 + mt) * 4 + kbl) * 128);
            uint2 bf[3][4];
            #pragma unroll
            for (int w = 0; w < 3; w++)
                #pragma unroll
                for (int nt = 0; nt < 4; nt++)
                    bf[w][nt] = *(const uint2*)(smu + S0 + bOff +
                                ((w * 16 + wn * 4 + nt) * 4 + kbl) * 64);
            // issue next chunk's copies under the MMAs (LSU || tensor)
            if (more) LOAD_QUARTER(ch + 2, stn, kbl);
            #pragma unroll
            for (int nt = 0; nt < 4; nt++) {
                MMA_F16(accL[0][nt], af[0][0], bf[0][nt]);
                MMA_F16(accL[1][nt], af[0][1], bf[0][nt]);
                MMA_F16(ac4s[0][nt], af[0][0], bf[2][nt]);
                MMA_F16(ac4s[1][nt], af[0][1], bf[2][nt]);
                MMA_F16(ac4e[0][nt], af[1][0], bf[2][nt]);
                MMA_F16(ac4e[1][nt], af[1][1], bf[2][nt]);
                MMA_F16(accL[0][nt], af[1][0], bf[1][nt]);
                MMA_F16(accL[1][nt], af[1][1], bf[1][nt]);
            }
        }
        // commit the 16 cp.asyncs issued this iteration (or an empty group:
        // keeps group accounting uniform for wait_group 1)
        asm volatile("cp.async.commit_group;" ::: "memory");
    }

    // epilogue
    const float* b4p  = span ? bh4 : bp4;
    const float* c12p = g_c12[span];
    float* outp = out + (size_t)span * MTOT * HID;

    #pragma unroll
    for (int mt = 0; mt < 2; mt++) {
        const int r0 = m0 + wm * 32 + mt * 16 + (lane >> 2);
        #pragma unroll
        for (int nt = 0; nt < 4; nt++) {
            const int o = n0 + wn * 32 + nt * 8 + (lane & 3) * 2;
            const float c0 = c12p[o],   c1 = c12p[o + 1];
            const float d0 = b4p[o],    d1 = b4p[o + 1];
            float v0 = accL[mt][nt][0] + c0 + (ac4s[mt][nt][0] + d0) * (ac4e[mt][nt][0] + d0);
            float v1 = accL[mt][nt][1] + c1 + (ac4s[mt][nt][1] + d1) * (ac4e[mt][nt][1] + d1);
            *(float2*)&outp[(size_t)r0 * HID + o] = make_float2(tanhf(v0), tanhf(v1));
            float v2 = accL[mt][nt][2] + c0 + (ac4s[mt][nt][2] + d0) * (ac4e[mt][nt][2] + d0);
            float v3 = accL[mt][nt][3] + c1 + (ac4s[mt][nt][3] + d1) * (ac4e[mt][nt][3] + d1);
            *(float2*)&outp[(size_t)(r0 + 8) * HID + o] = make_float2(tanhf(v2), tanhf(v3));
        }
    }
}

// ---------------- launch ----------------
extern "C" void kernel_launch(void* const* d_in, const int* in_sizes, int n_in,
                              void* d_out, int out_size) {
    const float* x    = (const float*)d_in[0];
    const void*  prem = d_in[1];
    const void*  hypo = d_in[2];
    const float* Wp1 = (const float*)d_in[3];
    const float* bp1 = (const float*)d_in[4];
    const float* Wp2 = (const float*)d_in[5];
    const float* bp2 = (const float*)d_in[6];
    const float* Wp3 = (const float*)d_in[7];
    const float* Wp4 = (const float*)d_in[9];
    const float* bp4 = (const float*)d_in[10];
    const float* Wh1 = (const float*)d_in[11];
    const float* bh1 = (const float*)d_in[12];
    const float* Wh2 = (const float*)d_in[13];
    const float* bh2 = (const float*)d_in[14];
    const float* Wh3 = (const float*)d_in[15];
    const float* Wh4 = (const float*)d_in[17];
    const float* bh4 = (const float*)d_in[18];
    float* out = (float*)d_out;

    prep_all<<<1280, 256>>>(x, prem, hypo,
                            Wp1, Wp2, Wp3, Wp4, Wh1, Wh2, Wh3, Wh4,
                            bp1, bp2, bh1, bh2);

    cudaFuncSetAttribute(gemm_kernel, cudaFuncAttributeMaxDynamicSharedMemorySize, SMEM_BYTES);
    gemm_kernel<<<dim3(HID / TN, MTOT / TM, 2), 256, SMEM_BYTES>>>(bp4, bh4, out);
}